// round 4
// baseline (speedup 1.0000x reference)
#include <cuda_runtime.h>
#include <cuda_fp16.h>

#define V 8192
#define E 262144
#define D 128
#define CAP 192
#define IDXBITS 18
#define IDXMASK 0x3FFFFu
#define RW 16   // rows (warps) per k_row block

// ---------------- scratch (device globals; no allocations allowed) ----------
__device__ __half   g_hwh[V * D];     // h @ W^T in fp16 (2 MB, L2-resident)
__device__ float    g_s1[V];          // hw[v] . att[:128]   (fp32)
__device__ float    g_s2[V];          // hw[v] . att[128:]   (fp32)
__device__ float    g_S[D];           // column sum of hw    (fp32)
__device__ int      g_cnt[V];         // per-src bucket cursors
__device__ uint2    g_ew[V * CAP];    // { (dst<<18)|edge_idx , half2(w,w) }
__device__ int      g_is64;           // edge_index dtype flag

// =================== K1: init + int64/int32 detection ========================
__global__ void k_init(const int* __restrict__ e32) {
    int b = blockIdx.x, t = threadIdx.x;
    if (b == 0) {
        __shared__ int flag;
        if (t == 0) flag = 0;
        __syncthreads();
        if (e32[2 * t + 1] != 0) atomicExch(&flag, 1);
        __syncthreads();
        if (t == 0) g_is64 = (flag == 0) ? 1 : 0;
    } else if (b == 1) {
        if (t < D) g_S[t] = 0.f;
    } else {
        g_cnt[(b - 2) * 256 + t] = 0;
    }
}

// =================== K2: GEMM hw = h @ W^T + fused epilogue ==================
__global__ void __launch_bounds__(256) k_gemm(const float* __restrict__ h,
                                              const float* __restrict__ Wm,
                                              const float* __restrict__ att) {
    __shared__ float sh_A[32][65];
    __shared__ float sh_B[32][132];
    __shared__ float s1s[64], s2s[64], cs[128];

    int tid = threadIdx.x;
    int tx = tid & 15, ty = tid >> 4;
    int row0 = blockIdx.x * 64;

    if (tid < 64) { s1s[tid] = 0.f; s2s[tid] = 0.f; }
    if (tid < 128) cs[tid] = 0.f;

    float acc[4][8];
#pragma unroll
    for (int r = 0; r < 4; r++)
#pragma unroll
        for (int c = 0; c < 8; c++) acc[r][c] = 0.f;

    for (int k0 = 0; k0 < 128; k0 += 32) {
        __syncthreads();
#pragma unroll
        for (int i = 0; i < 2; i++) {
            int idx = tid + i * 256;
            int row = idx >> 3, q = idx & 7;
            float4 v = *(const float4*)(h + (size_t)(row0 + row) * D + k0 + q * 4);
            sh_A[q * 4 + 0][row] = v.x;
            sh_A[q * 4 + 1][row] = v.y;
            sh_A[q * 4 + 2][row] = v.z;
            sh_A[q * 4 + 3][row] = v.w;
        }
#pragma unroll
        for (int i = 0; i < 4; i++) {
            int idx = tid + i * 256;
            int col = idx >> 3, q = idx & 7;
            float4 v = *(const float4*)(Wm + (size_t)col * D + k0 + q * 4);
            sh_B[q * 4 + 0][col] = v.x;
            sh_B[q * 4 + 1][col] = v.y;
            sh_B[q * 4 + 2][col] = v.z;
            sh_B[q * 4 + 3][col] = v.w;
        }
        __syncthreads();
#pragma unroll
        for (int k = 0; k < 32; k++) {
            float a0 = sh_A[k][ty * 4 + 0];
            float a1 = sh_A[k][ty * 4 + 1];
            float a2 = sh_A[k][ty * 4 + 2];
            float a3 = sh_A[k][ty * 4 + 3];
            float4 b0 = *(const float4*)&sh_B[k][tx * 8];
            float4 b1 = *(const float4*)&sh_B[k][tx * 8 + 4];
            float bv[8] = {b0.x, b0.y, b0.z, b0.w, b1.x, b1.y, b1.z, b1.w};
#pragma unroll
            for (int c = 0; c < 8; c++) {
                acc[0][c] += a0 * bv[c];
                acc[1][c] += a1 * bv[c];
                acc[2][c] += a2 * bv[c];
                acc[3][c] += a3 * bv[c];
            }
        }
    }
    __syncthreads();

#pragma unroll
    for (int r = 0; r < 4; r++) {
        int row = row0 + ty * 4 + r;
        __half2 h0 = __floats2half2_rn(acc[r][0], acc[r][1]);
        __half2 h1 = __floats2half2_rn(acc[r][2], acc[r][3]);
        __half2 h2 = __floats2half2_rn(acc[r][4], acc[r][5]);
        __half2 h3 = __floats2half2_rn(acc[r][6], acc[r][7]);
        uint4 u;
        u.x = *(unsigned*)&h0; u.y = *(unsigned*)&h1;
        u.z = *(unsigned*)&h2; u.w = *(unsigned*)&h3;
        *(uint4*)((__half*)g_hwh + (size_t)row * D + tx * 8) = u;
    }

    float4 A1a = *(const float4*)(att + tx * 8);
    float4 A1b = *(const float4*)(att + tx * 8 + 4);
    float4 A2a = *(const float4*)(att + D + tx * 8);
    float4 A2b = *(const float4*)(att + D + tx * 8 + 4);
    float a1v[8] = {A1a.x, A1a.y, A1a.z, A1a.w, A1b.x, A1b.y, A1b.z, A1b.w};
    float a2v[8] = {A2a.x, A2a.y, A2a.z, A2a.w, A2b.x, A2b.y, A2b.z, A2b.w};
#pragma unroll
    for (int r = 0; r < 4; r++) {
        float p1 = 0.f, p2 = 0.f;
#pragma unroll
        for (int c = 0; c < 8; c++) { p1 += acc[r][c] * a1v[c]; p2 += acc[r][c] * a2v[c]; }
        atomicAdd(&s1s[ty * 4 + r], p1);
        atomicAdd(&s2s[ty * 4 + r], p2);
    }
#pragma unroll
    for (int c = 0; c < 8; c++) {
        float q = acc[0][c] + acc[1][c] + acc[2][c] + acc[3][c];
        atomicAdd(&cs[tx * 8 + c], q);
    }
    __syncthreads();
    if (tid < 64) { g_s1[row0 + tid] = s1s[tid]; g_s2[row0 + tid] = s2s[tid]; }
    if (tid < 128) atomicAdd(&g_S[tid], cs[tid]);
}

// =================== K3: per-edge logit + bucket scatter =====================
__global__ void k_scatter(const int* __restrict__ e32) {
    int e = blockIdx.x * blockDim.x + threadIdx.x;
    if (e >= E) return;
    int src, dst;
    if (g_is64) {
        src = ((const int2*)e32)[e].x;
        dst = ((const int2*)e32)[E + e].x;
    } else {
        src = e32[e];
        dst = e32[E + e];
    }
    float a = g_s1[src] + g_s2[dst];
    a = a > 0.f ? a : 0.2f * a;                 // LeakyReLU(0.2)
    float w = expm1f(a);                        // exp(a) - 1
    int pos = atomicAdd(&g_cnt[src], 1);
    if (pos < CAP) {
        unsigned hb = __half_as_ushort(__float2half_rn(w));
        uint2 rec;
        rec.x = ((unsigned)dst << IDXBITS) | (unsigned)e;
        rec.y = hb | (hb << 16);                // half2 (w, w)
        g_ew[(size_t)src * CAP + pos] = rec;
    }
}

// =================== K4: dedup + half2-FMA gather + normalize ================
// One warp per row. Lanes 0-15 serve edge A of a pair, lanes 16-31 edge B;
// each lane loads 16B (8 halves) per edge; 4 edges/lane accumulated via HFMA2
// into half2, flushed to fp32 every 4-edge group.
__global__ void __launch_bounds__(32 * RW) k_row(float* __restrict__ out) {
    __shared__ uint2 sm[RW][CAP + 8];
    int wid = threadIdx.x >> 5, lane = threadIdx.x & 31;
    int row = blockIdx.x * RW + wid;
    int d = g_cnt[row];
    if (d > CAP) d = CAP;
    int dpad = (d + 7) & ~7;
    const uint2* bucket = g_ew + (size_t)row * CAP;

    for (int t = lane; t < dpad; t += 32)
        sm[wid][t] = (t < d) ? bucket[t] : make_uint2(0u, 0u);
    __syncwarp();

    // pass 1: dedup — keep only max original-edge-index per dst (last-write-wins)
    float dsum = 0.f;
    for (int j = lane; j < d; j += 32) {
        unsigned mx = sm[wid][j].x;
        unsigned dst = mx >> IDXBITS, idx = mx & IDXMASK;
        bool kept = true;
        for (int t = 0; t < d; t++) {
            unsigned m2 = sm[wid][t].x;
            if ((m2 >> IDXBITS) == dst && (m2 & IDXMASK) > idx) { kept = false; break; }
        }
        if (!kept) sm[wid][j].y = 0u;           // half2 zero
        else dsum += __half2float(__ushort_as_half((unsigned short)(sm[wid][j].y & 0xFFFFu)));
    }
    __syncwarp();

    // pass 2: gather with HFMA2 group accumulation
    float acc[8];
#pragma unroll
    for (int i = 0; i < 8; i++) acc[i] = 0.f;
    int half_ = lane >> 4;
    int cl = (lane & 15) * 8;
    const __half* hw = g_hwh;

    for (int t = 0; t < dpad; t += 8) {
        __half2 ha0 = __float2half2_rn(0.f), ha1 = ha0, ha2 = ha0, ha3 = ha0;
#pragma unroll
        for (int p = 0; p < 4; p++) {
            uint2 m = sm[wid][t + 2 * p + half_];
            __half2 w2 = *(__half2*)&m.y;
            uint4 v = *(const uint4*)(hw + (size_t)(m.x >> IDXBITS) * D + cl);
            ha0 = __hfma2(w2, *(__half2*)&v.x, ha0);
            ha1 = __hfma2(w2, *(__half2*)&v.y, ha1);
            ha2 = __hfma2(w2, *(__half2*)&v.z, ha2);
            ha3 = __hfma2(w2, *(__half2*)&v.w, ha3);
        }
        float2 f0 = __half22float2(ha0);
        float2 f1 = __half22float2(ha1);
        float2 f2 = __half22float2(ha2);
        float2 f3 = __half22float2(ha3);
        acc[0] += f0.x; acc[1] += f0.y;
        acc[2] += f1.x; acc[3] += f1.y;
        acc[4] += f2.x; acc[5] += f2.y;
        acc[6] += f3.x; acc[7] += f3.y;
    }

#pragma unroll
    for (int i = 0; i < 8; i++) acc[i] += __shfl_xor_sync(0xffffffffu, acc[i], 16);
#pragma unroll
    for (int o = 16; o; o >>= 1) dsum += __shfl_xor_sync(0xffffffffu, dsum, o);

    float inv = 1.f / ((float)V + dsum);
    if (lane < 16) {
        float4 Sa = *(const float4*)(g_S + cl);
        float4 Sb = *(const float4*)(g_S + cl + 4);
        float4 o0, o1;
        o0.x = (Sa.x + acc[0]) * inv; o0.y = (Sa.y + acc[1]) * inv;
        o0.z = (Sa.z + acc[2]) * inv; o0.w = (Sa.w + acc[3]) * inv;
        o1.x = (Sb.x + acc[4]) * inv; o1.y = (Sb.y + acc[5]) * inv;
        o1.z = (Sb.z + acc[6]) * inv; o1.w = (Sb.w + acc[7]) * inv;
        *(float4*)(out + (size_t)row * D + cl) = o0;
        *(float4*)(out + (size_t)row * D + cl + 4) = o1;
    }
}

// ----------------------------------------------------------------------------
extern "C" void kernel_launch(void* const* d_in, const int* in_sizes, int n_in,
                              void* d_out, int out_size) {
    const float* h   = (const float*)d_in[0];
    const int*   ei  = (const int*)d_in[1];
    const float* Wm  = (const float*)d_in[2];
    const float* att = (const float*)d_in[3];
    float* out = (float*)d_out;

    k_init<<<34, 256>>>(ei);
    k_gemm<<<V / 64, 256>>>(h, Wm, att);
    k_scatter<<<E / 256, 256>>>(ei);
    k_row<<<V / RW, 32 * RW>>>(out);
}

// round 5
// speedup vs baseline: 1.1696x; 1.1696x over previous
#include <cuda_runtime.h>
#include <cuda_fp16.h>

#define V 8192
#define E 262144
#define D 128
#define SLOTS 128           // hash slots per row (power of 2, >= ~2x max degree)

// ---------------- scratch (device globals; no allocations allowed) ----------
__device__ __half             g_hwh[V * D];        // h @ W^T in fp16 (2 MB)
__device__ float              g_s1[V];             // hw[v] . att[:128]
__device__ float              g_s2[V];             // hw[v] . att[128:]
__device__ float              g_Spart[128 * D];    // per-gemm-block colsum partials
__device__ float              g_S[D];              // reduced colsum
__device__ unsigned long long g_ew64[(size_t)V * SLOTS];  // hash: (idx+1)<<29|dst<<16|half(w)
__device__ int                g_is64;              // edge_index dtype flag

// =================== K1: GEMM hw = h @ W^T + fused epilogue + detect =========
__global__ void __launch_bounds__(256) k_gemm(const float* __restrict__ h,
                                              const float* __restrict__ Wm,
                                              const float* __restrict__ att,
                                              const int* __restrict__ e32) {
    __shared__ float sh_A[32][65];
    __shared__ float sh_B[32][132];
    __shared__ float s1s[64], s2s[64], cs[128];

    int tid = threadIdx.x;
    int tx = tid & 15, ty = tid >> 4;
    int row0 = blockIdx.x * 64;

    // int64/int32 detection (block 0): int64 values < 2^13 => odd words all 0
    if (blockIdx.x == 0) {
        __shared__ int flag;
        if (tid == 0) flag = 0;
        __syncthreads();
        if (e32[2 * tid + 1] != 0) atomicExch(&flag, 1);
        __syncthreads();
        if (tid == 0) g_is64 = (flag == 0) ? 1 : 0;
    }

    if (tid < 64) { s1s[tid] = 0.f; s2s[tid] = 0.f; }
    if (tid < 128) cs[tid] = 0.f;

    float acc[4][8];
#pragma unroll
    for (int r = 0; r < 4; r++)
#pragma unroll
        for (int c = 0; c < 8; c++) acc[r][c] = 0.f;

    for (int k0 = 0; k0 < 128; k0 += 32) {
        __syncthreads();
#pragma unroll
        for (int i = 0; i < 2; i++) {
            int idx = tid + i * 256;
            int row = idx >> 3, q = idx & 7;
            float4 v = *(const float4*)(h + (size_t)(row0 + row) * D + k0 + q * 4);
            sh_A[q * 4 + 0][row] = v.x;
            sh_A[q * 4 + 1][row] = v.y;
            sh_A[q * 4 + 2][row] = v.z;
            sh_A[q * 4 + 3][row] = v.w;
        }
#pragma unroll
        for (int i = 0; i < 4; i++) {
            int idx = tid + i * 256;
            int col = idx >> 3, q = idx & 7;
            float4 v = *(const float4*)(Wm + (size_t)col * D + k0 + q * 4);
            sh_B[q * 4 + 0][col] = v.x;
            sh_B[q * 4 + 1][col] = v.y;
            sh_B[q * 4 + 2][col] = v.z;
            sh_B[q * 4 + 3][col] = v.w;
        }
        __syncthreads();
#pragma unroll
        for (int k = 0; k < 32; k++) {
            float a0 = sh_A[k][ty * 4 + 0];
            float a1 = sh_A[k][ty * 4 + 1];
            float a2 = sh_A[k][ty * 4 + 2];
            float a3 = sh_A[k][ty * 4 + 3];
            float4 b0 = *(const float4*)&sh_B[k][tx * 8];
            float4 b1 = *(const float4*)&sh_B[k][tx * 8 + 4];
            float bv[8] = {b0.x, b0.y, b0.z, b0.w, b1.x, b1.y, b1.z, b1.w};
#pragma unroll
            for (int c = 0; c < 8; c++) {
                acc[0][c] += a0 * bv[c];
                acc[1][c] += a1 * bv[c];
                acc[2][c] += a2 * bv[c];
                acc[3][c] += a3 * bv[c];
            }
        }
    }
    __syncthreads();

#pragma unroll
    for (int r = 0; r < 4; r++) {
        int row = row0 + ty * 4 + r;
        __half2 h0 = __floats2half2_rn(acc[r][0], acc[r][1]);
        __half2 h1 = __floats2half2_rn(acc[r][2], acc[r][3]);
        __half2 h2 = __floats2half2_rn(acc[r][4], acc[r][5]);
        __half2 h3 = __floats2half2_rn(acc[r][6], acc[r][7]);
        uint4 u;
        u.x = *(unsigned*)&h0; u.y = *(unsigned*)&h1;
        u.z = *(unsigned*)&h2; u.w = *(unsigned*)&h3;
        *(uint4*)((__half*)g_hwh + (size_t)row * D + tx * 8) = u;
    }

    float4 A1a = *(const float4*)(att + tx * 8);
    float4 A1b = *(const float4*)(att + tx * 8 + 4);
    float4 A2a = *(const float4*)(att + D + tx * 8);
    float4 A2b = *(const float4*)(att + D + tx * 8 + 4);
    float a1v[8] = {A1a.x, A1a.y, A1a.z, A1a.w, A1b.x, A1b.y, A1b.z, A1b.w};
    float a2v[8] = {A2a.x, A2a.y, A2a.z, A2a.w, A2b.x, A2b.y, A2b.z, A2b.w};
#pragma unroll
    for (int r = 0; r < 4; r++) {
        float p1 = 0.f, p2 = 0.f;
#pragma unroll
        for (int c = 0; c < 8; c++) { p1 += acc[r][c] * a1v[c]; p2 += acc[r][c] * a2v[c]; }
        atomicAdd(&s1s[ty * 4 + r], p1);
        atomicAdd(&s2s[ty * 4 + r], p2);
    }
#pragma unroll
    for (int c = 0; c < 8; c++) {
        float q = acc[0][c] + acc[1][c] + acc[2][c] + acc[3][c];
        atomicAdd(&cs[tx * 8 + c], q);
    }
    __syncthreads();
    if (tid < 64) { g_s1[row0 + tid] = s1s[tid]; g_s2[row0 + tid] = s2s[tid]; }
    if (tid < 128) g_Spart[blockIdx.x * D + tid] = cs[tid];   // race-free partial
}

// =================== K2: per-edge logit + hash insert (dedup by atomicMax) ===
// Record: bits[0:16)=half(w), [16:29)=dst, [29:48)=edge_idx+1  (max idx wins)
__global__ void k_scatter(const int* __restrict__ e32) {
    // block 0 additionally reduces colsum partials -> g_S (k_row runs later)
    if (blockIdx.x == 0 && threadIdx.x < 128) {
        float s = 0.f;
#pragma unroll 8
        for (int b = 0; b < 128; b++) s += g_Spart[b * D + threadIdx.x];
        g_S[threadIdx.x] = s;
    }
    int e = blockIdx.x * blockDim.x + threadIdx.x;
    if (e >= E) return;
    int src, dst;
    if (g_is64) {
        src = ((const int2*)e32)[e].x;
        dst = ((const int2*)e32)[E + e].x;
    } else {
        src = e32[e];
        dst = e32[E + e];
    }
    float a = g_s1[src] + g_s2[dst];
    a = a > 0.f ? a : 0.2f * a;                       // LeakyReLU(0.2)
    float w = expm1f(a);                              // exp(a) - 1
    unsigned wh = (unsigned)__half_as_ushort(__float2half_rn(w));
    unsigned long long rec = ((unsigned long long)(unsigned)(e + 1) << 29)
                           | ((unsigned long long)(unsigned)dst << 16) | wh;
    unsigned slot = ((unsigned)dst * 2654435761u) >> 25;   // 7-bit hash
    unsigned long long* tab = g_ew64 + (size_t)src * SLOTS;
    for (int probe = 0; probe < SLOTS; probe++) {
        unsigned long long old = atomicCAS(&tab[slot], 0ULL, rec);
        if (old == 0ULL) break;                            // claimed empty slot
        if (((unsigned)(old >> 16) & 0x1FFFu) == (unsigned)dst) {
            atomicMax(&tab[slot], rec);                    // last-write-wins
            break;
        }
        slot = (slot + 1) & (SLOTS - 1);
    }
}

// =================== K3: slot scan + compact + gather + normalize ============
// One warp per row. Scan the row's 128 hash slots (coalesced), compact the
// non-empty records via ballot into shared, zero the slots for the next graph
// replay, then pair-gather fp16 rows with fp32 FFMA (R3 geometry).
__global__ void __launch_bounds__(256, 5) k_row(float* __restrict__ out) {
    __shared__ uint2 sm[8][SLOTS];     // {dst, float bits of w}
    int wid = threadIdx.x >> 5, lane = threadIdx.x & 31;
    int row = blockIdx.x * 8 + wid;
    unsigned long long* tab = g_ew64 + (size_t)row * SLOTS;

    float dsum = 0.f;
    int cnt = 0;
#pragma unroll
    for (int rnd = 0; rnd < SLOTS / 32; rnd++) {
        int s = rnd * 32 + lane;
        unsigned long long v = tab[s];
        tab[s] = 0ULL;                                   // replay-safe re-zero
        unsigned mask = __ballot_sync(0xffffffffu, v != 0ULL);
        if (v != 0ULL) {
            int pos = cnt + __popc(mask & ((1u << lane) - 1u));
            float w = __half2float(__ushort_as_half((unsigned short)(v & 0xFFFFu)));
            sm[wid][pos] = make_uint2((unsigned)(v >> 16) & 0x1FFFu,
                                      __float_as_uint(w));
            dsum += w;
        }
        cnt += __popc(mask);
    }
    int dpad = (cnt + 7) & ~7;
    for (int t = cnt + lane; t < dpad; t += 32)
        sm[wid][t] = make_uint2(0u, 0u);                 // harmless pad (w=0)
    __syncwarp();

    // pair-gather: lanes 0-15 edge A, 16-31 edge B; 16B (8 halves) per lane
    float acc[8];
#pragma unroll
    for (int i = 0; i < 8; i++) acc[i] = 0.f;
    int half_ = lane >> 4;
    int cl = (lane & 15) * 8;
    const __half* hw = g_hwh;

    for (int t = 0; t < dpad; t += 8) {
#pragma unroll
        for (int p = 0; p < 4; p++) {
            uint2 m = sm[wid][t + 2 * p + half_];
            float w = __uint_as_float(m.y);
            uint4 v = *(const uint4*)(hw + (size_t)m.x * D + cl);
            float2 f0 = __half22float2(*(__half2*)&v.x);
            float2 f1 = __half22float2(*(__half2*)&v.y);
            float2 f2 = __half22float2(*(__half2*)&v.z);
            float2 f3 = __half22float2(*(__half2*)&v.w);
            acc[0] += w * f0.x; acc[1] += w * f0.y;
            acc[2] += w * f1.x; acc[3] += w * f1.y;
            acc[4] += w * f2.x; acc[5] += w * f2.y;
            acc[6] += w * f3.x; acc[7] += w * f3.y;
        }
    }

#pragma unroll
    for (int i = 0; i < 8; i++) acc[i] += __shfl_xor_sync(0xffffffffu, acc[i], 16);
#pragma unroll
    for (int o = 16; o; o >>= 1) dsum += __shfl_xor_sync(0xffffffffu, dsum, o);

    float inv = 1.f / ((float)V + dsum);
    if (lane < 16) {
        float4 Sa = *(const float4*)(g_S + cl);
        float4 Sb = *(const float4*)(g_S + cl + 4);
        float4 o0, o1;
        o0.x = (Sa.x + acc[0]) * inv; o0.y = (Sa.y + acc[1]) * inv;
        o0.z = (Sa.z + acc[2]) * inv; o0.w = (Sa.w + acc[3]) * inv;
        o1.x = (Sb.x + acc[4]) * inv; o1.y = (Sb.y + acc[5]) * inv;
        o1.z = (Sb.z + acc[6]) * inv; o1.w = (Sb.w + acc[7]) * inv;
        *(float4*)(out + (size_t)row * D + cl) = o0;
        *(float4*)(out + (size_t)row * D + cl + 4) = o1;
    }
}

// ----------------------------------------------------------------------------
extern "C" void kernel_launch(void* const* d_in, const int* in_sizes, int n_in,
                              void* d_out, int out_size) {
    const float* h   = (const float*)d_in[0];
    const int*   ei  = (const int*)d_in[1];
    const float* Wm  = (const float*)d_in[2];
    const float* att = (const float*)d_in[3];
    float* out = (float*)d_out;

    k_gemm<<<V / 64, 256>>>(h, Wm, att, ei);
    k_scatter<<<E / 256, 256>>>(ei);
    k_row<<<V / 8, 256>>>(out);
}